// round 1
// baseline (speedup 1.0000x reference)
#include <cuda_runtime.h>
#include <math.h>

#define Bn   8
#define Cn   112
#define Hn   64
#define Wn   64
#define On   112
#define Gn   14
#define K2n  9
#define PGC  378          // 3*G*K2
#define HWn  4096         // 64*64
#define CKn  1008         // C*K2

// Scratch (statically allocated: no cudaMalloc allowed)
__device__ float g_pg[(size_t)Bn * PGC * HWn];     // 49.5 MB: offset/mask conv output
__device__ float g_samp[(size_t)Bn * CKn * HWn];   // 132 MB:  sampled*mask, layout [b][c*9+k][p]

// ---------------------------------------------------------------------------
// Kernel 1: pg = conv3x3(x, pg_weight) + pg_bias     (stride 1, pad 1)
// Tiled direct conv: 16x16 spatial tile, 8-input-channel chunks,
// 6 output channels per thread. 256 threads/block.
// ---------------------------------------------------------------------------
__global__ void __launch_bounds__(256) pg_conv_kernel(
    const float* __restrict__ x,
    const float* __restrict__ w,
    const float* __restrict__ bias)
{
    __shared__ float sx[8][18][18];   // 8 ci x (16+2)^2 halo tile
    __shared__ float sw[6][8][9];     // 6 co x 8 ci x 9 taps

    const int tid = threadIdx.x;              // 0..255
    const int tx  = tid & 15;
    const int ty  = tid >> 4;
    const int tile = blockIdx.x;              // 0..15 (4x4 tiles of 16x16)
    const int gx0 = (tile & 3) << 4;
    const int gy0 = (tile >> 2) << 4;
    const int co0 = blockIdx.y * 6;           // 63 co-blocks * 6 = 378
    const int b   = blockIdx.z;

    float acc[6] = {0.f, 0.f, 0.f, 0.f, 0.f, 0.f};

    for (int ci0 = 0; ci0 < Cn; ci0 += 8) {
        // cooperative load of x halo tile (zero-padded borders)
        for (int i = tid; i < 8 * 18 * 18; i += 256) {
            int ci = i / 324;
            int r  = i - ci * 324;
            int yy = r / 18;
            int xx = r - yy * 18;
            int gy = gy0 + yy - 1;
            int gx = gx0 + xx - 1;
            float v = 0.f;
            if (gy >= 0 && gy < Hn && gx >= 0 && gx < Wn)
                v = x[(((size_t)b * Cn + ci0 + ci) * Hn + gy) * Wn + gx];
            sx[ci][yy][xx] = v;
        }
        // cooperative load of weights: 6*8*9 = 432
        for (int i = tid; i < 432; i += 256) {
            int co = i / 72;
            int r  = i - co * 72;
            int ci = r / 9;
            int kk = r - ci * 9;
            sw[co][ci][kk] = w[((size_t)(co0 + co) * Cn + ci0 + ci) * 9 + kk];
        }
        __syncthreads();

        #pragma unroll
        for (int ci = 0; ci < 8; ci++) {
            #pragma unroll
            for (int kk = 0; kk < 9; kk++) {
                float xv = sx[ci][ty + kk / 3][tx + kk % 3];
                #pragma unroll
                for (int co = 0; co < 6; co++)
                    acc[co] += xv * sw[co][ci][kk];   // sw read is warp-uniform (broadcast)
            }
        }
        __syncthreads();
    }

    const int oy = gy0 + ty;
    const int ox = gx0 + tx;
    #pragma unroll
    for (int co = 0; co < 6; co++)
        g_pg[(((size_t)b * PGC + co0 + co) * Hn + oy) * Wn + ox] = acc[co] + bias[co0 + co];
}

// ---------------------------------------------------------------------------
// Kernel 2: deformable bilinear sampling with sigmoid mask.
// One thread per output pixel for one group g; loops over the 9 taps and the
// group's 8 channels. Writes g_samp[b][(g*8+cc)*9+k][p]  (coalesced over p).
//
// Channel map (since concat([oh,ow]) == pg[:, :252]):
//   dy(g,k)=pg[g*18+2k], dx(g,k)=pg[g*18+2k+1], mask(g,k)=sigmoid(pg[252+g*9+k])
// ---------------------------------------------------------------------------
__global__ void __launch_bounds__(256) sample_kernel(const float* __restrict__ x)
{
    const int p  = blockIdx.x * 256 + threadIdx.x;  // 0..4095
    const int g  = blockIdx.y;                      // 0..13
    const int b  = blockIdx.z;                      // 0..7
    const int ho = p >> 6;
    const int wo = p & 63;

    const float* pgb = g_pg + (size_t)b * PGC * HWn;

    #pragma unroll
    for (int k = 0; k < 9; k++) {
        const float dy = pgb[(size_t)(g * 18 + 2 * k) * HWn + p];
        const float dx = pgb[(size_t)(g * 18 + 2 * k + 1) * HWn + p];
        const float mv = pgb[(size_t)(252 + g * 9 + k) * HWn + p];
        const float mask = 1.0f / (1.0f + __expf(-mv));

        const float yf = (float)(ho - 1 + k / 3) + dy;
        const float xf = (float)(wo - 1 + k % 3) + dx;
        const float y0f = floorf(yf);
        const float x0f = floorf(xf);
        const int y0 = (int)y0f;
        const int x0 = (int)x0f;
        const float wy1 = yf - y0f, wx1 = xf - x0f;
        const float wy0 = 1.f - wy1, wx0 = 1.f - wx1;

        const bool vy0 = (y0 >= 0)     && (y0 < Hn);
        const bool vy1 = (y0 + 1 >= 0) && (y0 + 1 < Hn);
        const bool vx0 = (x0 >= 0)     && (x0 < Wn);
        const bool vx1 = (x0 + 1 >= 0) && (x0 + 1 < Wn);

        const int y0c = min(max(y0, 0), Hn - 1);
        const int y1c = min(max(y0 + 1, 0), Hn - 1);
        const int x0c = min(max(x0, 0), Wn - 1);
        const int x1c = min(max(x0 + 1, 0), Wn - 1);

        // fold validity + mask into the corner weights -> branchless inner loop
        const float w00 = (vy0 && vx0) ? wy0 * wx0 * mask : 0.f;
        const float w01 = (vy0 && vx1) ? wy0 * wx1 * mask : 0.f;
        const float w10 = (vy1 && vx0) ? wy1 * wx0 * mask : 0.f;
        const float w11 = (vy1 && vx1) ? wy1 * wx1 * mask : 0.f;

        const int i00 = y0c * Wn + x0c;
        const int i01 = y0c * Wn + x1c;
        const int i10 = y1c * Wn + x0c;
        const int i11 = y1c * Wn + x1c;

        #pragma unroll
        for (int cc = 0; cc < 8; cc++) {
            const float* img = x + ((size_t)b * Cn + g * 8 + cc) * HWn;
            const float v = img[i00] * w00 + img[i01] * w01
                          + img[i10] * w10 + img[i11] * w11;
            g_samp[((size_t)b * CKn + (size_t)(g * 8 + cc) * 9 + k) * HWn + p] = v;
        }
    }
}

// ---------------------------------------------------------------------------
// Kernel 3: out[b][o][p] = sum_ck W[o][ck] * samp[b][ck][p] + bias[o]
// Tiled fp32 GEMM: 56(M) x 64(N) x 16(K) tiles, 7x2 register tile per thread.
// A-tile reads are warp-uniform broadcasts; B-tile reads conflict-free.
// ---------------------------------------------------------------------------
__global__ void __launch_bounds__(256) gemm_kernel(
    const float* __restrict__ w,      // (O, C, 3, 3) == (O, 1008) row-major
    const float* __restrict__ bias,
    float* __restrict__ out)
{
    __shared__ float sW[16][56];
    __shared__ float sS[16][64];

    const int tid = threadIdx.x;
    const int tn  = tid & 31;     // 0..31  (pixel lane)
    const int tm  = tid >> 5;     // 0..7   (row group)
    const int p0  = blockIdx.x * 64;
    const int m0  = blockIdx.y * 56;
    const int b   = blockIdx.z;

    const float* Sb = g_samp + (size_t)b * CKn * HWn;

    float acc[7][2];
    #pragma unroll
    for (int i = 0; i < 7; i++) { acc[i][0] = 0.f; acc[i][1] = 0.f; }

    for (int k0 = 0; k0 < CKn; k0 += 16) {
        for (int i = tid; i < 56 * 16; i += 256) {
            int m = i >> 4, kk = i & 15;
            sW[kk][m] = w[(size_t)(m0 + m) * CKn + k0 + kk];
        }
        for (int i = tid; i < 16 * 64; i += 256) {
            int kk = i >> 6, pp = i & 63;
            sS[kk][pp] = Sb[(size_t)(k0 + kk) * HWn + p0 + pp];
        }
        __syncthreads();

        #pragma unroll
        for (int kk = 0; kk < 16; kk++) {
            float a[7], bv0, bv1;
            #pragma unroll
            for (int i = 0; i < 7; i++) a[i] = sW[kk][tm * 7 + i];
            bv0 = sS[kk][tn];
            bv1 = sS[kk][tn + 32];
            #pragma unroll
            for (int i = 0; i < 7; i++) {
                acc[i][0] += a[i] * bv0;
                acc[i][1] += a[i] * bv1;
            }
        }
        __syncthreads();
    }

    #pragma unroll
    for (int i = 0; i < 7; i++) {
        const int m = m0 + tm * 7 + i;
        const float bs = bias[m];
        out[((size_t)b * On + m) * HWn + p0 + tn]      = acc[i][0] + bs;
        out[((size_t)b * On + m) * HWn + p0 + tn + 32] = acc[i][1] + bs;
    }
}

// ---------------------------------------------------------------------------
extern "C" void kernel_launch(void* const* d_in, const int* in_sizes, int n_in,
                              void* d_out, int out_size)
{
    const float* x   = (const float*)d_in[0];   // (8,112,64,64)
    const float* pgw = (const float*)d_in[1];   // (378,112,3,3)
    const float* pgb = (const float*)d_in[2];   // (378,)
    const float* wt  = (const float*)d_in[3];   // (112,112,3,3)
    const float* bs  = (const float*)d_in[4];   // (112,)
    float* out = (float*)d_out;                 // (8,112,64,64)

    pg_conv_kernel<<<dim3(16, 63, 8), 256>>>(x, pgw, pgb);
    sample_kernel<<<dim3(16, 14, 8), 256>>>(x);
    gemm_kernel<<<dim3(64, 2, 8), 256>>>(wt, bs, out);
}

// round 13
// speedup vs baseline: 1.4004x; 1.4004x over previous
#include <cuda_runtime.h>
#include <math.h>

#define Bn   8
#define Cn   112
#define Hn   64
#define Wn   64
#define On   112
#define Gn   14
#define K2n  9
#define PGC  378          // 3*G*K2
#define HWn  4096         // 64*64
#define CKn  1008         // C*K2

// Scratch (statically allocated: no cudaMalloc allowed)
__device__ float g_pg[(size_t)Bn * PGC * HWn];     // 49.5 MB: offset/mask conv output
__device__ float g_samp[(size_t)Bn * CKn * HWn];   // 132 MB:  sampled*mask, layout [b][c*9+k][p]

// ---------------------------------------------------------------------------
// Kernel 1: pg = conv3x3(x, pg_weight) + pg_bias   (stride 1, pad 1)
// v2: 32x32 spatial tile, 8-ci chunks, each thread computes 2x2 pixels x 6 co
// (24 accumulators). The 4x4 x-window lives in registers across all 9 taps,
// so LDS:FFMA drops from 1.17 to ~0.32 (was L1-throughput bound at 95.8%).
// ---------------------------------------------------------------------------
__global__ void __launch_bounds__(256) pg_conv_kernel(
    const float* __restrict__ x,
    const float* __restrict__ w,
    const float* __restrict__ bias)
{
    __shared__ __align__(16) float sx[8][34][34];  // 8 ci x (32+2)^2 halo
    __shared__ float sw[6][8][9];                  // 6 co x 8 ci x 9 taps

    const int tid = threadIdx.x;              // 0..255
    const int tx  = tid & 15;                 // pixel-pair col
    const int ty  = tid >> 4;                 // pixel-pair row
    const int tile = blockIdx.x;              // 0..3 (2x2 tiles of 32x32)
    const int gx0 = (tile & 1) << 5;
    const int gy0 = (tile >> 1) << 5;
    const int co0 = blockIdx.y * 6;           // 63 co-blocks * 6 = 378
    const int b   = blockIdx.z;

    float acc[2][2][6];
    #pragma unroll
    for (int py = 0; py < 2; py++)
        #pragma unroll
        for (int px = 0; px < 2; px++)
            #pragma unroll
            for (int co = 0; co < 6; co++) acc[py][px][co] = 0.f;

    for (int ci0 = 0; ci0 < Cn; ci0 += 8) {
        // cooperative load of x halo tile (zero-padded borders): 8*34*34 = 9248
        for (int i = tid; i < 8 * 34 * 34; i += 256) {
            int ci = i / 1156;
            int r  = i - ci * 1156;
            int yy = r / 34;
            int xx = r - yy * 34;
            int gy = gy0 + yy - 1;
            int gx = gx0 + xx - 1;
            float v = 0.f;
            if ((unsigned)gy < (unsigned)Hn && (unsigned)gx < (unsigned)Wn)
                v = x[(((size_t)b * Cn + ci0 + ci) * Hn + gy) * Wn + gx];
            sx[ci][yy][xx] = v;
        }
        // cooperative load of weights: 6*8*9 = 432
        for (int i = tid; i < 432; i += 256) {
            int co = i / 72;
            int r  = i - co * 72;
            int ci = r / 9;
            int kk = r - ci * 9;
            sw[co][ci][kk] = w[((size_t)(co0 + co) * Cn + ci0 + ci) * 9 + kk];
        }
        __syncthreads();

        for (int ci = 0; ci < 8; ci++) {
            // 4x4 x-window into registers (8B-aligned paired loads)
            float xv[4][4];
            #pragma unroll
            for (int yy = 0; yy < 4; yy++) {
                float2 pa = *(const float2*)&sx[ci][ty * 2 + yy][tx * 2];
                float2 pb = *(const float2*)&sx[ci][ty * 2 + yy][tx * 2 + 2];
                xv[yy][0] = pa.x; xv[yy][1] = pa.y;
                xv[yy][2] = pb.x; xv[yy][3] = pb.y;
            }
            #pragma unroll
            for (int kk = 0; kk < 9; kk++) {
                const int ky = kk / 3, kx = kk % 3;
                float wr[6];
                #pragma unroll
                for (int co = 0; co < 6; co++) wr[co] = sw[co][ci][kk];  // broadcast
                #pragma unroll
                for (int py = 0; py < 2; py++)
                    #pragma unroll
                    for (int px = 0; px < 2; px++) {
                        const float xval = xv[py + ky][px + kx];
                        #pragma unroll
                        for (int co = 0; co < 6; co++)
                            acc[py][px][co] += xval * wr[co];
                    }
            }
        }
        __syncthreads();
    }

    const int ox = gx0 + tx * 2;
    #pragma unroll
    for (int co = 0; co < 6; co++) {
        const float bv = bias[co0 + co];
        #pragma unroll
        for (int py = 0; py < 2; py++) {
            const int oy = gy0 + ty * 2 + py;
            float2 o2 = make_float2(acc[py][0][co] + bv, acc[py][1][co] + bv);
            *(float2*)&g_pg[(((size_t)b * PGC + co0 + co) * Hn + oy) * Wn + ox] = o2;
        }
    }
}

// ---------------------------------------------------------------------------
// Kernel 2: deformable bilinear sampling with sigmoid mask.
// One thread per output pixel for one group g; loops over the 9 taps and the
// group's 8 channels. Writes g_samp[b][(g*8+cc)*9+k][p]  (coalesced over p).
//
// Channel map (since concat([oh,ow]) == pg[:, :252]):
//   dy(g,k)=pg[g*18+2k], dx(g,k)=pg[g*18+2k+1], mask(g,k)=sigmoid(pg[252+g*9+k])
// ---------------------------------------------------------------------------
__global__ void __launch_bounds__(256) sample_kernel(const float* __restrict__ x)
{
    const int p  = blockIdx.x * 256 + threadIdx.x;  // 0..4095
    const int g  = blockIdx.y;                      // 0..13
    const int b  = blockIdx.z;                      // 0..7
    const int ho = p >> 6;
    const int wo = p & 63;

    const float* pgb = g_pg + (size_t)b * PGC * HWn;

    #pragma unroll
    for (int k = 0; k < 9; k++) {
        const float dy = pgb[(size_t)(g * 18 + 2 * k) * HWn + p];
        const float dx = pgb[(size_t)(g * 18 + 2 * k + 1) * HWn + p];
        const float mv = pgb[(size_t)(252 + g * 9 + k) * HWn + p];
        const float mask = 1.0f / (1.0f + __expf(-mv));

        const float yf = (float)(ho - 1 + k / 3) + dy;
        const float xf = (float)(wo - 1 + k % 3) + dx;
        const float y0f = floorf(yf);
        const float x0f = floorf(xf);
        const int y0 = (int)y0f;
        const int x0 = (int)x0f;
        const float wy1 = yf - y0f, wx1 = xf - x0f;
        const float wy0 = 1.f - wy1, wx0 = 1.f - wx1;

        const bool vy0 = (y0 >= 0)     && (y0 < Hn);
        const bool vy1 = (y0 + 1 >= 0) && (y0 + 1 < Hn);
        const bool vx0 = (x0 >= 0)     && (x0 < Wn);
        const bool vx1 = (x0 + 1 >= 0) && (x0 + 1 < Wn);

        const int y0c = min(max(y0, 0), Hn - 1);
        const int y1c = min(max(y0 + 1, 0), Hn - 1);
        const int x0c = min(max(x0, 0), Wn - 1);
        const int x1c = min(max(x0 + 1, 0), Wn - 1);

        // fold validity + mask into corner weights -> branchless inner loop
        const float w00 = (vy0 && vx0) ? wy0 * wx0 * mask : 0.f;
        const float w01 = (vy0 && vx1) ? wy0 * wx1 * mask : 0.f;
        const float w10 = (vy1 && vx0) ? wy1 * wx0 * mask : 0.f;
        const float w11 = (vy1 && vx1) ? wy1 * wx1 * mask : 0.f;

        const int i00 = y0c * Wn + x0c;
        const int i01 = y0c * Wn + x1c;
        const int i10 = y1c * Wn + x0c;
        const int i11 = y1c * Wn + x1c;

        #pragma unroll
        for (int cc = 0; cc < 8; cc++) {
            const float* img = x + ((size_t)b * Cn + g * 8 + cc) * HWn;
            const float v = img[i00] * w00 + img[i01] * w01
                          + img[i10] * w10 + img[i11] * w11;
            g_samp[((size_t)b * CKn + (size_t)(g * 8 + cc) * 9 + k) * HWn + p] = v;
        }
    }
}

// ---------------------------------------------------------------------------
// Kernel 3: out[b][o][p] = sum_ck W[o][ck] * samp[b][ck][p] + bias[o]
// v2: 56(M) x 128(N) x 16(K) tiles, 7x4 register tile per thread with float4
// B loads: per k-step 7 broadcast LDS + 1 LDS.128 feed 28 FFMA (ratio 0.29).
// ---------------------------------------------------------------------------
__global__ void __launch_bounds__(256) gemm_kernel(
    const float* __restrict__ w,      // (O, C, 3, 3) == (O, 1008) row-major
    const float* __restrict__ bias,
    float* __restrict__ out)
{
    __shared__ float sW[16][56];
    __shared__ __align__(16) float sS[16][128];

    const int tid = threadIdx.x;
    const int tn  = tid & 31;     // pixel lane: 4 consecutive px each
    const int tm  = tid >> 5;     // row group (warp id): 7 rows each
    const int p0  = blockIdx.x * 128;
    const int m0  = blockIdx.y * 56;
    const int b   = blockIdx.z;

    const float* Sb = g_samp + (size_t)b * CKn * HWn;

    float acc[7][4];
    #pragma unroll
    for (int j = 0; j < 7; j++)
        #pragma unroll
        for (int q = 0; q < 4; q++) acc[j][q] = 0.f;

    for (int k0 = 0; k0 < CKn; k0 += 16) {
        // A tile: 56x16 (coalesced global rows of 16)
        for (int i = tid; i < 56 * 16; i += 256) {
            int m = i >> 4, kk = i & 15;
            sW[kk][m] = w[(size_t)(m0 + m) * CKn + k0 + kk];
        }
        // B tile: 16x128 as float4 (512 float4 loads)
        for (int i = tid; i < 512; i += 256) {
            int kk = i >> 5;
            int pp = (i & 31) << 2;
            *(float4*)&sS[kk][pp] =
                *(const float4*)&Sb[(size_t)(k0 + kk) * HWn + p0 + pp];
        }
        __syncthreads();

        #pragma unroll
        for (int kk = 0; kk < 16; kk++) {
            float a[7];
            #pragma unroll
            for (int j = 0; j < 7; j++) a[j] = sW[kk][tm * 7 + j];  // broadcast
            const float4 bv = *(const float4*)&sS[kk][tn * 4];
            #pragma unroll
            for (int j = 0; j < 7; j++) {
                acc[j][0] += a[j] * bv.x;
                acc[j][1] += a[j] * bv.y;
                acc[j][2] += a[j] * bv.z;
                acc[j][3] += a[j] * bv.w;
            }
        }
        __syncthreads();
    }

    #pragma unroll
    for (int j = 0; j < 7; j++) {
        const int m = m0 + tm * 7 + j;
        const float bs = bias[m];
        float4 o = make_float4(acc[j][0] + bs, acc[j][1] + bs,
                               acc[j][2] + bs, acc[j][3] + bs);
        *(float4*)&out[((size_t)b * On + m) * HWn + p0 + tn * 4] = o;
    }
}

// ---------------------------------------------------------------------------
extern "C" void kernel_launch(void* const* d_in, const int* in_sizes, int n_in,
                              void* d_out, int out_size)
{
    const float* x   = (const float*)d_in[0];   // (8,112,64,64)
    const float* pgw = (const float*)d_in[1];   // (378,112,3,3)
    const float* pgb = (const float*)d_in[2];   // (378,)
    const float* wt  = (const float*)d_in[3];   // (112,112,3,3)
    const float* bs  = (const float*)d_in[4];   // (112,)
    float* out = (float*)d_out;                 // (8,112,64,64)

    pg_conv_kernel<<<dim3(4, 63, 8), 256>>>(x, pgw, pgb);
    sample_kernel<<<dim3(16, 14, 8), 256>>>(x);
    gemm_kernel<<<dim3(32, 2, 8), 256>>>(wt, bs, out);
}